// round 14
// baseline (speedup 1.0000x reference)
#include <cuda_runtime.h>
#include <cuda_fp16.h>
#include <cstdint>

#define Ss 2048
#define Ee 1024
#define Hh 16
#define Dd 64

// ---------------- device scratch ------------------------------------------
__device__ __half g_xh[(size_t)4096 * 1024];
__device__ __half g_wT[(size_t)4 * 1024 * 1024];    // [mat][n][k]
__device__ __half g_Qh[(size_t)32 * Ss * Dd];       // [bh][s][d], pre-scaled by 0.125*log2e
__device__ __half g_Kh[(size_t)32 * Ss * Dd];
__device__ __half g_Vh[(size_t)32 * Ss * Dd];
__device__ __half g_Oh[(size_t)4096 * 1024];        // [b*S+s][h*64+d]

// ---------------- helpers --------------------------------------------------
__device__ __forceinline__ void mma_f16(float c[4],
                                        const uint32_t a[4],
                                        uint32_t b0, uint32_t b1) {
    asm volatile(
        "mma.sync.aligned.m16n8k16.row.col.f32.f16.f16.f32 "
        "{%0,%1,%2,%3},{%4,%5,%6,%7},{%8,%9},{%0,%1,%2,%3};"
        : "+f"(c[0]), "+f"(c[1]), "+f"(c[2]), "+f"(c[3])
        : "r"(a[0]), "r"(a[1]), "r"(a[2]), "r"(a[3]), "r"(b0), "r"(b1));
}
__device__ __forceinline__ uint32_t lds_addr(const void* p) {
    return (uint32_t)__cvta_generic_to_shared(p);
}
__device__ __forceinline__ void ldsm4(uint32_t r[4], uint32_t a) {
    asm volatile("ldmatrix.sync.aligned.m8n8.x4.shared.b16 {%0,%1,%2,%3}, [%4];"
        : "=r"(r[0]), "=r"(r[1]), "=r"(r[2]), "=r"(r[3]) : "r"(a));
}
__device__ __forceinline__ void ldsm4t(uint32_t r[4], uint32_t a) {
    asm volatile("ldmatrix.sync.aligned.m8n8.x4.trans.shared.b16 {%0,%1,%2,%3}, [%4];"
        : "=r"(r[0]), "=r"(r[1]), "=r"(r[2]), "=r"(r[3]) : "r"(a));
}
__device__ __forceinline__ float ex2f(float x) {
    float r;
    asm("ex2.approx.f32 %0, %1;" : "=f"(r) : "f"(x));
    return r;
}
__device__ __forceinline__ void cp16(__half* dst_sm, const __half* src) {
    asm volatile("cp.async.cg.shared.global [%0], [%1], 16;"
        :: "r"(lds_addr(dst_sm)), "l"(src));
}
#define CP_COMMIT() asm volatile("cp.async.commit_group;" ::: "memory")
#define CP_WAIT1()  asm volatile("cp.async.wait_group 1;" ::: "memory")
#define CP_WAIT0()  asm volatile("cp.async.wait_group 0;" ::: "memory")

// ===========================================================================
// Fused pre-pass: z<4 -> transpose+round W_z tiles; z>=4 -> round x chunk.
// ===========================================================================
__global__ __launch_bounds__(256) void prepass(
    const float* __restrict__ x,
    const float* __restrict__ Wq, const float* __restrict__ Wk,
    const float* __restrict__ Wv, const float* __restrict__ Wo)
{
    const int tx = threadIdx.x, ty = threadIdx.y;
    const int z = blockIdx.z;
    if (z >= 4) {
        int i = ((z - 4) * 1024 + blockIdx.y * 32 + blockIdx.x) * 256 + ty * 32 + tx;
        g_xh[i] = __float2half(x[i]);
        return;
    }
    __shared__ float t[32][33];
    const float* W = (z == 0) ? Wq : (z == 1) ? Wk : (z == 2) ? Wv : Wo;
    const int bx = blockIdx.x, by = blockIdx.y;
#pragma unroll
    for (int i = 0; i < 32; i += 8)
        t[ty + i][tx] = W[(size_t)(by * 32 + ty + i) * Ee + bx * 32 + tx];
    __syncthreads();
    const size_t base = (size_t)z * Ee * Ee;
#pragma unroll
    for (int i = 0; i < 32; i += 8) {
        int n = bx * 32 + ty + i, k = by * 32 + tx;
        g_wT[base + (size_t)n * Ee + k] = __float2half(t[tx][ty + i]);
    }
}

// ===========================================================================
// fp16 GEMM, occupancy build: tile 128x64, warp tile 32x32, 3-stage cp.async,
// target 3 CTAs/SM. Pitch 40 halfs. Stage = 128x32 A + 64x32 B = 15360 B.
// ===========================================================================
#define GP 40
#define G_A 0
#define G_B (128 * GP)                  // 5120
#define GSTG (G_B + 64 * GP)            // 7680 halfs per stage
#define GEMM_SMEM (3 * GSTG * 2)        // 46080 B

struct GemmAcc { float a[2][4][4]; };

__device__ __forceinline__ void gemm128_mainloop(
    const __half* __restrict__ A_g, const __half* __restrict__ B_g,
    __half* sm, GemmAcc& C)
{
    const int tid = threadIdx.x;
    const int wid = tid >> 5, lane = tid & 31;
    const int grp = lane >> 3, rr = lane & 7;
    const int wm = (wid & 3) * 32, wn = (wid >> 2) * 32;
    const int rA = tid >> 1, cA = (tid & 1) * 16;   // A staging: 2 cp16/thread
    const int rB = tid >> 2, cB = (tid & 3) * 8;    // B staging: 1 cp16/thread

    const int aoff = (wm + (grp & 1) * 8 + rr) * GP + (grp >> 1) * 8;
    const int boff = (wn + rr) * GP + grp * 8;

    auto issue = [&](int kc) {
        __half* buf = sm + (kc % 3) * GSTG;
        const int k0 = kc * 32;
        cp16(buf + G_A + rA * GP + cA,     A_g + (size_t)rA * Ee + k0 + cA);
        cp16(buf + G_A + rA * GP + cA + 8, A_g + (size_t)rA * Ee + k0 + cA + 8);
        cp16(buf + G_B + rB * GP + cB,     B_g + (size_t)rB * Ee + k0 + cB);
        CP_COMMIT();
    };

    issue(0);
    issue(1);

    for (int kc = 0; kc < 32; kc++) {
        if (kc < 31) CP_WAIT1(); else CP_WAIT0();
        __syncthreads();
        if (kc + 2 < 32) issue(kc + 2);

        __half* buf = sm + (kc % 3) * GSTG;
        uint32_t bf[4][4];
#pragma unroll
        for (int nf = 0; nf < 4; nf++)
            ldsm4(bf[nf], lds_addr(buf + G_B + boff + nf * 8 * GP));
#pragma unroll
        for (int ks = 0; ks < 2; ks++) {
            uint32_t af[2][4];
#pragma unroll
            for (int mf = 0; mf < 2; mf++)
                ldsm4(af[mf], lds_addr(buf + G_A + aoff + mf * 16 * GP + ks * 16));
#pragma unroll
            for (int nf = 0; nf < 4; nf++) {
                uint32_t b0 = bf[nf][ks * 2], b1 = bf[nf][ks * 2 + 1];
#pragma unroll
                for (int mf = 0; mf < 2; mf++)
                    mma_f16(C.a[mf][nf], af[mf], b0, b1);
            }
        }
    }
}

__global__ __launch_bounds__(256, 3) void gemm_qkv() {
    extern __shared__ __half smg[];
    const int tid = threadIdx.x;
    const int wid = tid >> 5, lane = tid & 31;
    const int g = lane >> 2, t4 = lane & 3;
    const int wm = (wid & 3) * 32, wn = (wid >> 2) * 32;
    const int n0 = blockIdx.x * 64, m0 = blockIdx.y * 128, z = blockIdx.z;

    GemmAcc C = {};
    gemm128_mainloop(g_xh + (size_t)m0 * Ee,
                     g_wT + ((size_t)z * Ee + n0) * Ee, smg, C);

    // Q pre-scaled by D^-1/2 * log2(e) for exp2-domain softmax
    const float qs = (z == 0) ? 0.125f * 1.4426950408889634f : 1.0f;
    __half* Oh = (z == 0) ? g_Qh : (z == 1) ? g_Kh : g_Vh;

#pragma unroll
    for (int mf = 0; mf < 2; mf++)
#pragma unroll
        for (int nf = 0; nf < 4; nf++) {
            int col = n0 + wn + nf * 8 + t4 * 2;
            int h = col >> 6, d = col & 63;
#pragma unroll
            for (int hi = 0; hi < 2; hi++) {
                int row = m0 + wm + mf * 16 + g + hi * 8;
                int b = row >> 11, s = row & (Ss - 1);
                size_t di = (((size_t)(b * Hh + h)) * Ss + s) * Dd + d;
                *(__half2*)&Oh[di] =
                    __half2(__float2half(C.a[mf][nf][hi * 2] * qs),
                            __float2half(C.a[mf][nf][hi * 2 + 1] * qs));
            }
        }
}

__global__ __launch_bounds__(256, 3) void gemm_proj(const float* __restrict__ bo,
                                                    float* __restrict__ out) {
    extern __shared__ __half smg[];
    const int tid = threadIdx.x;
    const int wid = tid >> 5, lane = tid & 31;
    const int g = lane >> 2, t4 = lane & 3;
    const int wm = (wid & 3) * 32, wn = (wid >> 2) * 32;
    const int n0 = blockIdx.x * 64, m0 = blockIdx.y * 128;

    GemmAcc C = {};
    gemm128_mainloop(g_Oh + (size_t)m0 * Ee,
                     g_wT + ((size_t)3 * Ee + n0) * Ee, smg, C);

#pragma unroll
    for (int mf = 0; mf < 2; mf++)
#pragma unroll
        for (int nf = 0; nf < 4; nf++) {
            int col = n0 + wn + nf * 8 + t4 * 2;
            float2 bias = *(const float2*)&bo[col];
#pragma unroll
            for (int hi = 0; hi < 2; hi++) {
                int row = m0 + wm + mf * 16 + g + hi * 8;
                *(float2*)&out[(size_t)row * Ee + col] =
                    make_float2(C.a[mf][nf][hi * 2] + bias.x,
                                C.a[mf][nf][hi * 2 + 1] + bias.y);
            }
        }
}

// ===========================================================================
// Attention: fp16 flash attention, exp2-domain softmax, 3-stage cp.async
// K/V pipeline. V staged natural [s][d]; PV B-frags via ldmatrix.trans.
// 8 warps x 16 q-rows. Pitch 72 halfs. (unchanged this round)
// ===========================================================================
#define AP2 72
#define A_P 0
#define ASTG 4608                        // 64x72 halfs per tensor tile
#define A_S0 9216
#define ATTN_SMEM ((9216 + 3 * 2 * ASTG) * 2)   // 72 KB

__global__ __launch_bounds__(256) void attn_f16() {
    extern __shared__ __half sma[];
    const int tid = threadIdx.x;
    const int wid = tid >> 5, lane = tid & 31;
    const int g = lane >> 2, t4 = lane & 3;
    const int grp = lane >> 3, rr = lane & 7;
    const int bh = blockIdx.y;
    const int qb = gridDim.x - 1 - blockIdx.x;   // heavy tiles first
    const int q0 = qb * 128;
    const int wrow = wid * 16;

    const __half* Qg = g_Qh + (size_t)bh * Ss * Dd;
    const __half* Kg = g_Kh + (size_t)bh * Ss * Dd;
    const __half* Vg = g_Vh + (size_t)bh * Ss * Dd;

    // stage Q into (future) P region: 128 x 64
#pragma unroll
    for (int t = 0; t < 4; t++) {
        int slot = t * 256 + tid;
        int r = slot >> 3, c = (slot & 7) * 8;
        *(uint4*)(sma + A_P + r * AP2 + c) =
            *(const uint4*)(Qg + (size_t)(q0 + r) * Dd + c);
    }

    const int ktmax = 2 * qb + 2;

    auto issue = [&](int kt) {
        __half* buf = sma + A_S0 + (kt % 3) * 2 * ASTG;
        const int k0 = kt * 64;
#pragma unroll
        for (int t = 0; t < 2; t++) {
            int slot = t * 256 + tid;
            int r = slot >> 3, c = (slot & 7) * 8;
            cp16(buf + r * AP2 + c, Kg + (size_t)(k0 + r) * Dd + c);
            cp16(buf + ASTG + r * AP2 + c, Vg + (size_t)(k0 + r) * Dd + c);
        }
        CP_COMMIT();
    };

    issue(0);
    issue(1);           // ktmax >= 2 always

    __syncthreads();    // Q staged before frag loads
    const int qoff = (wrow + (grp & 1) * 8 + rr) * AP2 + (grp >> 1) * 8;
    uint32_t qf[4][4];
#pragma unroll
    for (int ks = 0; ks < 4; ks++)
        ldsm4(qf[ks], lds_addr(sma + A_P + qoff + ks * 16));

    const int boff = rr * AP2 + grp * 8;            // K B-frags ([n][k] layout)
    const int voff = (grp * 8 + rr) * AP2;          // V trans B-frags ([k][n] layout)

    float m_i[2] = {-1e30f, -1e30f}, l_i[2] = {0.f, 0.f};
    float o[8][4] = {};

    for (int kt = 0; kt < ktmax; kt++) {
        const int k0 = kt * 64;
        if (kt + 1 < ktmax) CP_WAIT1(); else CP_WAIT0();
        __syncthreads();
        if (kt + 2 < ktmax) issue(kt + 2);

        __half* kbuf = sma + A_S0 + (kt % 3) * 2 * ASTG;
        __half* vbuf = kbuf + ASTG;

        // ---- S = Q K^T (exp2-domain) ----
        float sc[8][4] = {};
#pragma unroll
        for (int nf = 0; nf < 8; nf++) {
            uint32_t k8[8];
            ldsm4(k8,     lds_addr(kbuf + boff + nf * 8 * AP2));
            ldsm4(k8 + 4, lds_addr(kbuf + boff + nf * 8 * AP2 + 32));
#pragma unroll
            for (int ks = 0; ks < 4; ks++)
                mma_f16(sc[nf], qf[ks], k8[ks * 2], k8[ks * 2 + 1]);
        }

        // ---- causal mask ----
        if (kt >= 2 * qb) {
#pragma unroll
            for (int nf = 0; nf < 8; nf++)
#pragma unroll
                for (int j = 0; j < 4; j++) {
                    int col = k0 + nf * 8 + t4 * 2 + (j & 1);
                    int row = q0 + wrow + g + (j >> 1) * 8;
                    if (col > row) sc[nf][j] = -1e30f;
                }
        }

        // ---- online softmax (log2 domain) ----
#pragma unroll
        for (int hi = 0; hi < 2; hi++) {
            const int j0 = hi * 2;
            float mrow = -1e30f;
#pragma unroll
            for (int nf = 0; nf < 8; nf++)
                mrow = fmaxf(mrow, fmaxf(sc[nf][j0], sc[nf][j0 + 1]));
            mrow = fmaxf(mrow, __shfl_xor_sync(0xffffffffu, mrow, 1));
            mrow = fmaxf(mrow, __shfl_xor_sync(0xffffffffu, mrow, 2));
            float mnew = fmaxf(m_i[hi], mrow);
            float corr = ex2f(m_i[hi] - mnew);
            m_i[hi] = mnew;
            float ps = 0.f;
#pragma unroll
            for (int nf = 0; nf < 8; nf++) {
                float e0 = ex2f(sc[nf][j0] - mnew);
                float e1 = ex2f(sc[nf][j0 + 1] - mnew);
                sc[nf][j0] = e0; sc[nf][j0 + 1] = e1;
                ps += e0 + e1;
            }
            ps += __shfl_xor_sync(0xffffffffu, ps, 1);
            ps += __shfl_xor_sync(0xffffffffu, ps, 2);
            l_i[hi] = l_i[hi] * corr + ps;
#pragma unroll
            for (int nf = 0; nf < 8; nf++) {
                o[nf][j0] *= corr;
                o[nf][j0 + 1] *= corr;
            }
        }

        // ---- P -> smem (warp-private rows) ----
#pragma unroll
        for (int nf = 0; nf < 8; nf++) {
            int col = nf * 8 + t4 * 2;
            *(__half2*)(sma + A_P + (wrow + g) * AP2 + col) =
                __half2(__float2half(sc[nf][0]), __float2half(sc[nf][1]));
            *(__half2*)(sma + A_P + (wrow + g + 8) * AP2 + col) =
                __half2(__float2half(sc[nf][2]), __float2half(sc[nf][3]));
        }
        __syncwarp();

        // ---- O += P V  (V via ldmatrix.trans from [s][d]) ----
        uint32_t pf[4][4];
#pragma unroll
        for (int ks = 0; ks < 4; ks++)
            ldsm4(pf[ks], lds_addr(sma + A_P + qoff + ks * 16));
#pragma unroll
        for (int nf = 0; nf < 8; nf++) {
            uint32_t v8[8];
            ldsm4t(v8,     lds_addr(vbuf + voff + nf * 8));
            ldsm4t(v8 + 4, lds_addr(vbuf + voff + 32 * AP2 + nf * 8));
#pragma unroll
            for (int ks = 0; ks < 4; ks++)
                mma_f16(o[nf], pf[ks], v8[ks * 2], v8[ks * 2 + 1]);
        }
    }

    // ---- epilogue: O/l -> fp16, proj layout [b*S+s][h*64+d] ----
    const int b = bh >> 4, h = bh & 15;
    float inv_lo = 1.0f / l_i[0];
    float inv_hi = 1.0f / l_i[1];
#pragma unroll
    for (int nf = 0; nf < 8; nf++) {
        int srow = q0 + wrow + g;
        int col = h * 64 + nf * 8 + t4 * 2;
        size_t r0i = ((size_t)b * Ss + srow) * Ee + col;
        size_t r1i = ((size_t)b * Ss + srow + 8) * Ee + col;
        *(__half2*)&g_Oh[r0i] =
            __half2(__float2half(o[nf][0] * inv_lo), __float2half(o[nf][1] * inv_lo));
        *(__half2*)&g_Oh[r1i] =
            __half2(__float2half(o[nf][2] * inv_hi), __float2half(o[nf][3] * inv_hi));
    }
}

// ---------------------------------------------------------------------------
extern "C" void kernel_launch(void* const* d_in, const int* in_sizes, int n_in,
                              void* d_out, int out_size)
{
    const float* x  = (const float*)d_in[0];
    const float* Wq = (const float*)d_in[1];
    const float* Wk = (const float*)d_in[2];
    const float* Wv = (const float*)d_in[3];
    const float* Wo = (const float*)d_in[4];
    const float* bo = (const float*)d_in[5];
    float* out = (float*)d_out;

    cudaFuncSetAttribute(gemm_qkv,  cudaFuncAttributeMaxDynamicSharedMemorySize, GEMM_SMEM);
    cudaFuncSetAttribute(gemm_proj, cudaFuncAttributeMaxDynamicSharedMemorySize, GEMM_SMEM);
    cudaFuncSetAttribute(attn_f16,  cudaFuncAttributeMaxDynamicSharedMemorySize, ATTN_SMEM);

    prepass<<<dim3(32, 32, 20), dim3(32, 8)>>>(x, Wq, Wk, Wv, Wo);
    gemm_qkv<<<dim3(16, 32, 3), 256, GEMM_SMEM>>>();
    attn_f16<<<dim3(16, 32), 256, ATTN_SMEM>>>();
    gemm_proj<<<dim3(16, 32), 256, GEMM_SMEM>>>(bo, out);
}